// round 6
// baseline (speedup 1.0000x reference)
#include <cuda_runtime.h>
#include <cstdint>

#define F_    128
#define NE_   132
#define MT_   128          // rows per tile
#define NKP   68           // kpairs (K padded to 136)
#define NCOL  136
#define PADB  136          // B row stride (words)
#define XS    132          // x stage row stride (words)
#define CS    20           // chi stage row stride (words)
#define NTHR  512

// smem byte offsets
#define OFF_X0   0u                 // [128][132] f32 : 67584
#define OFF_X1   67584u
#define OFF_CHI0 135168u            // [128][20] f32 : 10240
#define OFF_CHI1 145408u
#define OFF_B    155648u            // [68][136] u32 (fp16x2) : 36992
#define OFF_BIAS 192640u            // 136 f32
#define SMEM_REQ 193184u

__device__ __forceinline__ uint32_t s2u(const void* p) {
    uint32_t a;
    asm("{ .reg .u64 t; cvta.to.shared.u64 t, %1; cvt.u32.u64 %0, t; }"
        : "=r"(a) : "l"(p));
    return a;
}
__device__ __forceinline__ uint32_t packh(float v0, float v1) {
    uint32_t r;
    asm("cvt.rn.f16x2.f32 %0, %1, %2;" : "=r"(r) : "f"(v1), "f"(v0));
    return r;
}
__device__ __forceinline__ void mma16(float* c, const uint32_t* a,
                                      uint32_t b0, uint32_t b1) {
    asm volatile(
        "mma.sync.aligned.m16n8k16.row.col.f32.f16.f16.f32 "
        "{%0,%1,%2,%3}, {%4,%5,%6,%7}, {%8,%9}, {%0,%1,%2,%3};"
        : "+f"(c[0]), "+f"(c[1]), "+f"(c[2]), "+f"(c[3])
        : "r"(a[0]), "r"(a[1]), "r"(a[2]), "r"(a[3]), "r"(b0), "r"(b1));
}
__device__ __forceinline__ void mma8(float* c, uint32_t a0, uint32_t a1,
                                     uint32_t b0) {
    asm volatile(
        "mma.sync.aligned.m16n8k8.row.col.f32.f16.f16.f32 "
        "{%0,%1,%2,%3}, {%4,%5}, {%6}, {%0,%1,%2,%3};"
        : "+f"(c[0]), "+f"(c[1]), "+f"(c[2]), "+f"(c[3])
        : "r"(a0), "r"(a1), "r"(b0));
}
__device__ __forceinline__ void cpa16(uint32_t dst, const void* src, int sz) {
    asm volatile("cp.async.cg.shared.global [%0], [%1], 16, %2;"
                 :: "r"(dst), "l"(src), "r"(sz) : "memory");
}

__device__ __forceinline__ void issue_tile(uint32_t xdst, uint32_t cdst,
                                           const float* x, const float* chi,
                                           int m0, int rv, int tid) {
#pragma unroll
    for (int i = 0; i < 8; i++) {
        int c = tid + i * NTHR;           // 4096 16B chunks of x tile
        int row = c >> 5, seg = c & 31;
        const char* src = (const char*)x + (size_t)(m0 + row) * 512 + seg * 16;
        int sz = 16;
        if (row >= rv) { src = (const char*)x; sz = 0; }
        cpa16(xdst + row * (XS * 4) + seg * 16, src, sz);
    }
    {
        int c = tid;                      // 512 chunks of chi tile
        int row = c >> 2, seg = c & 3;
        const char* src = (const char*)chi + (size_t)(m0 + row) * 64 + seg * 16;
        int sz = 16;
        if (row >= rv) { src = (const char*)chi; sz = 0; }
        cpa16(cdst + row * (CS * 4) + seg * 16, src, sz);
    }
    asm volatile("cp.async.commit_group;" ::: "memory");
}

// per-half tile compute: NT n-tiles starting at column col0.
template<int NT>
__device__ __forceinline__ void tile_compute(
    const float* __restrict__ xsm, const float* __restrict__ csm,
    const uint32_t* __restrict__ Bh, const float* __restrict__ bias,
    float* __restrict__ a1, float* __restrict__ chiout,
    int m0, int rv, int r0, int r1, int g, int t4, int col0)
{
    float acc[NT][4];
#pragma unroll
    for (int nt = 0; nt < NT; nt++) {
        int col = col0 + nt * 8 + t4 * 2;
        acc[nt][0] = bias[col];     acc[nt][1] = bias[col + 1];
        acc[nt][2] = bias[col];     acc[nt][3] = bias[col + 1];
    }

    // main K: 8 x k16
#pragma unroll 1
    for (int ks = 0; ks < 8; ks++) {
        const int kb = 16 * ks + 2 * t4;
        float2 a00 = *(const float2*)&xsm[r0 * XS + kb];
        float2 a10 = *(const float2*)&xsm[r1 * XS + kb];
        float2 a01 = *(const float2*)&xsm[r0 * XS + kb + 8];
        float2 a11 = *(const float2*)&xsm[r1 * XS + kb + 8];
        uint32_t a[4];
        a[0] = packh(a00.x, a00.y);
        a[1] = packh(a10.x, a10.y);
        a[2] = packh(a01.x, a01.y);
        a[3] = packh(a11.x, a11.y);
        const uint32_t* B0 = &Bh[(8 * ks + t4) * PADB + col0];
        const uint32_t* B1 = &Bh[(8 * ks + t4 + 4) * PADB + col0];
#pragma unroll
        for (int nt = 0; nt < NT; nt++) {
            int c = nt * 8 + g;
            mma16(acc[nt], a, B0[c], B1[c]);
        }
    }

    // tail k8: d_chi (K cols 128..131); t4>=2 lanes feed zero kpairs 66/67
    {
        float s0a = 0.f, s1a = 0.f, s0b = 0.f, s1b = 0.f;
        if (t4 == 0) {
            float4 c0 = *(const float4*)&csm[r0 * CS];
            float4 d0 = *(const float4*)&csm[r1 * CS];
            s0a = c0.x * c0.x;
            s1a = c0.y * c0.y + c0.z * c0.z + c0.w * c0.w;
            s0b = d0.x * d0.x;
            s1b = d0.y * d0.y + d0.z * d0.z + d0.w * d0.w;
        } else if (t4 == 1) {
            float4 c1 = *(const float4*)&csm[r0 * CS + 4];
            float4 c2 = *(const float4*)&csm[r0 * CS + 8];
            float4 c3 = *(const float4*)&csm[r0 * CS + 12];
            s0a = c1.x * c1.x + c1.y * c1.y + c1.z * c1.z + c1.w * c1.w
                + c2.x * c2.x;
            s1a = c2.y * c2.y + c2.z * c2.z + c2.w * c2.w
                + c3.x * c3.x + c3.y * c3.y + c3.z * c3.z + c3.w * c3.w;
            float4 d1 = *(const float4*)&csm[r1 * CS + 4];
            float4 d2 = *(const float4*)&csm[r1 * CS + 8];
            float4 d3 = *(const float4*)&csm[r1 * CS + 12];
            s0b = d1.x * d1.x + d1.y * d1.y + d1.z * d1.z + d1.w * d1.w
                + d2.x * d2.x;
            s1b = d2.y * d2.y + d2.z * d2.z + d2.w * d2.w
                + d3.x * d3.x + d3.y * d3.y + d3.z * d3.z + d3.w * d3.w;
        }
        uint32_t ta0 = packh(s0a, s1a);
        uint32_t ta1 = packh(s0b, s1b);
        const uint32_t* Bt = &Bh[(64 + t4) * PADB + col0];
#pragma unroll
        for (int nt = 0; nt < NT; nt++) {
            int c = nt * 8 + g;
            mma8(acc[nt], ta0, ta1, Bt[c]);
        }
    }

    // epilogue: a1 from first 8 n-tiles
    {
        float* ab = a1 + (size_t)m0 * F_ + col0;
        const bool v0 = (r0 < rv), v1 = (r1 < rv);
#pragma unroll
        for (int nt = 0; nt < 8; nt++) {
            int col = nt * 8 + t4 * 2;
            if (v0) *(float2*)&ab[(size_t)r0 * F_ + col] =
                        make_float2(acc[nt][0], acc[nt][1]);
            if (v1) *(float2*)&ab[(size_t)r1 * F_ + col] =
                        make_float2(acc[nt][2], acc[nt][3]);
        }
    }
    // chi_out: only the NT==9 half owns cols 128..131 (its 9th n-tile)
    if (NT == 9) {
        float c0 = acc[8][0], c1 = acc[8][1];
        float c2 = acc[8][2], c3 = acc[8][3];
        float o0 = __shfl_xor_sync(0xFFFFFFFFu, c0, 1);
        float o2 = __shfl_xor_sync(0xFFFFFFFFu, c2, 1);
        if (t4 == 0) {
            // (b0,b1) own, b2 from neighbor
            float b0r[2] = {c0, c2}, b1r[2] = {c1, c3}, b2r[2] = {o0, o2};
            int rr[2] = {r0, r1};
#pragma unroll
            for (int h = 0; h < 2; h++) {
                if (rr[h] < rv) {
                    const float* cr = &csm[rr[h] * CS];
                    float4 ca = *(const float4*)&cr[0];
                    float4 cb = *(const float4*)&cr[4];
                    float4 u, w;
                    u.x = b0r[h] * ca.x; u.y = b1r[h] * ca.y;
                    u.z = b1r[h] * ca.z; u.w = b1r[h] * ca.w;
                    w.x = b2r[h] * cb.x; w.y = b2r[h] * cb.y;
                    w.z = b2r[h] * cb.z; w.w = b2r[h] * cb.w;
                    float* op = &chiout[(size_t)(m0 + rr[h]) * 16];
                    *(float4*)&op[0] = u;
                    *(float4*)&op[4] = w;
                }
            }
        } else if (t4 == 1) {
            float b2r[2] = {c0, c2}, b3r[2] = {c1, c3};
            int rr[2] = {r0, r1};
#pragma unroll
            for (int h = 0; h < 2; h++) {
                if (rr[h] < rv) {
                    const float* cr = &csm[rr[h] * CS];
                    float4 ca = *(const float4*)&cr[8];
                    float4 cb = *(const float4*)&cr[12];
                    float4 u, w;
                    u.x = b2r[h] * ca.x; u.y = b3r[h] * ca.y;
                    u.z = b3r[h] * ca.z; u.w = b3r[h] * ca.w;
                    w.x = b3r[h] * cb.x; w.y = b3r[h] * cb.y;
                    w.z = b3r[h] * cb.z; w.w = b3r[h] * cb.w;
                    float* op = &chiout[(size_t)(m0 + rr[h]) * 16];
                    *(float4*)&op[8]  = u;
                    *(float4*)&op[12] = w;
                }
            }
        }
    }
}

__global__ __launch_bounds__(NTHR)
void ib_mma_kernel(const float* __restrict__ x, const float* __restrict__ chi,
                   const float* __restrict__ W, const float* __restrict__ b,
                   float* __restrict__ a1, float* __restrict__ chiout, int n)
{
    extern __shared__ char sm[];
    const uint32_t smb = s2u(sm);
    float*    xs[2]  = {(float*)(sm + OFF_X0), (float*)(sm + OFF_X1)};
    float*    cs[2]  = {(float*)(sm + OFF_CHI0), (float*)(sm + OFF_CHI1)};
    const uint32_t xsu[2] = {smb + OFF_X0, smb + OFF_X1};
    const uint32_t csu[2] = {smb + OFF_CHI0, smb + OFF_CHI1};
    uint32_t* Bh   = (uint32_t*)(sm + OFF_B);
    float*    bias = (float*)(sm + OFF_BIAS);

    const int tid  = threadIdx.x;
    const int wid  = tid >> 5;
    const int lane = tid & 31;
    const int g    = lane >> 2;
    const int t4   = lane & 3;
    const int band = wid & 7;          // row band
    const int half = wid >> 3;         // N half: 0 -> cols 0-63, 1 -> 64-135
    const int r0   = band * 16 + g;
    const int r1   = r0 + 8;
    const int col0 = half * 64;

    const int ntiles = (n + MT_ - 1) / MT_;
    int t = blockIdx.x;

    // prologue: start tile 0 fetch immediately
    {
        int m0 = t * MT_;
        int rv = (n - m0 < MT_) ? (n - m0) : MT_;
        issue_tile(xsu[0], csu[0], x, chi, m0, rv, tid);
    }

    // one-time: W -> fp16x2 B table, bias
    for (int e = tid; e < NKP * NCOL; e += NTHR) {
        int kp = e / NCOL, c = e - kp * NCOL;
        int k0 = 2 * kp, k1 = k0 + 1;
        float w0 = (k0 < NE_ && c < NE_) ? W[k0 * NE_ + c] : 0.f;
        float w1 = (k1 < NE_ && c < NE_) ? W[k1 * NE_ + c] : 0.f;
        Bh[kp * PADB + c] = packh(w0, w1);
    }
    if (tid < NCOL) bias[tid] = (tid < NE_) ? b[tid] : 0.f;

    for (int i = 0; t < ntiles; i++, t += gridDim.x) {
        const int buf = i & 1;
        const int m0 = t * MT_;
        const int rv = (n - m0 < MT_) ? (n - m0) : MT_;
        const int tn = t + gridDim.x;

        if (tn < ntiles) {
            int m0n = tn * MT_;
            int rvn = (n - m0n < MT_) ? (n - m0n) : MT_;
            issue_tile(xsu[buf ^ 1], csu[buf ^ 1], x, chi, m0n, rvn, tid);
            asm volatile("cp.async.wait_group 1;" ::: "memory");
        } else {
            asm volatile("cp.async.wait_group 0;" ::: "memory");
        }
        __syncthreads();   // tile t data visible

        if (half == 0)
            tile_compute<8>(xs[buf], cs[buf], Bh, bias, a1, chiout,
                            m0, rv, r0, r1, g, t4, col0);
        else
            tile_compute<9>(xs[buf], cs[buf], Bh, bias, a1, chiout,
                            m0, rv, r0, r1, g, t4, col0);

        __syncthreads();   // all reads of buf done before refill
    }
}

extern "C" void kernel_launch(void* const* d_in, const int* in_sizes, int n_in,
                              void* d_out, int out_size) {
    const float* x   = (const float*)d_in[0];
    const float* chi = (const float*)d_in[1];
    // d_in[2] = point_mask (all ones; unused by the math)
    const float* W   = (const float*)d_in[3];
    const float* b   = (const float*)d_in[4];

    const int n = in_sizes[0] / F_;
    float* out    = (float*)d_out;
    float* a1     = out;
    float* chiout = out + (size_t)n * F_;

    cudaFuncSetAttribute(ib_mma_kernel,
                         cudaFuncAttributeMaxDynamicSharedMemorySize, SMEM_REQ);
    int ntiles = (n + MT_ - 1) / MT_;
    int grid = ntiles < 152 ? ntiles : 152;
    ib_mma_kernel<<<grid, NTHR, SMEM_REQ>>>(x, chi, W, b, a1, chiout, n);
}

// round 7
// speedup vs baseline: 1.5217x; 1.5217x over previous
#include <cuda_runtime.h>
#include <cstdint>

#define F_     128
#define NE_    132
#define MT_    128
#define NTHR   512
#define ASTR_B 272u          // A row stride bytes (136 f16, 17x16B: ldm conflict-free)
#define BSTR_B 272u          // Bt row stride bytes
#define CSTR_W 20            // chi stage row stride (words)

#define OFF_A    0u          // [128][272B] : 34816
#define OFF_BT   34816u      // [136][272B] : 36992
#define OFF_CHI  71808u      // [128][20] f32 : 10240
#define OFF_BIAS 82048u      // 136 f32 : 544
#define SMEM_REQ 82592u

__device__ __forceinline__ uint32_t s2u(const void* p) {
    uint32_t a;
    asm("{ .reg .u64 t; cvta.to.shared.u64 t, %1; cvt.u32.u64 %0, t; }"
        : "=r"(a) : "l"(p));
    return a;
}
__device__ __forceinline__ uint32_t packh(float v0, float v1) {
    uint32_t r;
    asm("cvt.rn.f16x2.f32 %0, %1, %2;" : "=r"(r) : "f"(v1), "f"(v0));
    return r;
}
__device__ __forceinline__ void mma16(float* c, const uint32_t* a,
                                      uint32_t b0, uint32_t b1) {
    asm volatile(
        "mma.sync.aligned.m16n8k16.row.col.f32.f16.f16.f32 "
        "{%0,%1,%2,%3}, {%4,%5,%6,%7}, {%8,%9}, {%0,%1,%2,%3};"
        : "+f"(c[0]), "+f"(c[1]), "+f"(c[2]), "+f"(c[3])
        : "r"(a[0]), "r"(a[1]), "r"(a[2]), "r"(a[3]), "r"(b0), "r"(b1));
}
__device__ __forceinline__ void mma8(float* c, uint32_t a0, uint32_t a1,
                                     uint32_t b0) {
    asm volatile(
        "mma.sync.aligned.m16n8k8.row.col.f32.f16.f16.f32 "
        "{%0,%1,%2,%3}, {%4,%5}, {%6}, {%0,%1,%2,%3};"
        : "+f"(c[0]), "+f"(c[1]), "+f"(c[2]), "+f"(c[3])
        : "r"(a0), "r"(a1), "r"(b0));
}
__device__ __forceinline__ void ldm4(uint32_t* r, uint32_t a) {
    asm volatile("ldmatrix.sync.aligned.m8n8.x4.shared.b16 {%0,%1,%2,%3}, [%4];"
                 : "=r"(r[0]), "=r"(r[1]), "=r"(r[2]), "=r"(r[3]) : "r"(a));
}
__device__ __forceinline__ void ldm2(uint32_t* r, uint32_t a) {
    asm volatile("ldmatrix.sync.aligned.m8n8.x2.shared.b16 {%0,%1}, [%2];"
                 : "=r"(r[0]), "=r"(r[1]) : "r"(a));
}
__device__ __forceinline__ void ldm1(uint32_t* r, uint32_t a) {
    asm volatile("ldmatrix.sync.aligned.m8n8.x1.shared.b16 {%0}, [%1];"
                 : "=r"(r[0]) : "r"(a));
}

// per-warp tile compute: 2 m-tiles (32 rows) x NTQ n-tiles at quarter q.
template<int NTQ>
__device__ __forceinline__ void compute_tile(
    uint32_t aA0, uint32_t aA1, uint32_t aB0, uint32_t aB1, uint32_t aB4,
    uint32_t aAt, uint32_t aBt, uint32_t aBt4,
    const float* __restrict__ bias, const float* __restrict__ csm,
    float* __restrict__ a1, float* __restrict__ chiout,
    int m0, int rv, int band, int q, int g, int t4)
{
    float acc[2][NTQ][4];
#pragma unroll
    for (int mt = 0; mt < 2; mt++)
#pragma unroll
        for (int nt = 0; nt < NTQ; nt++) {
            int col = q * 32 + nt * 8 + t4 * 2;
            float b0 = bias[col], b1 = bias[col + 1];
            acc[mt][nt][0] = b0; acc[mt][nt][1] = b1;
            acc[mt][nt][2] = b0; acc[mt][nt][3] = b1;
        }

#pragma unroll 2
    for (int ks = 0; ks < 8; ks++) {
        uint32_t A0[4], A1[4], Bp0[4], Bp1[4], B4[2];
        ldm4(A0, aA0 + ks * 32);
        ldm4(A1, aA1 + ks * 32);
        ldm4(Bp0, aB0 + ks * 32);
        ldm4(Bp1, aB1 + ks * 32);
        if (NTQ == 5) ldm2(B4, aB4 + ks * 32);
        mma16(acc[0][0], A0, Bp0[0], Bp0[1]);
        mma16(acc[1][0], A1, Bp0[0], Bp0[1]);
        mma16(acc[0][1], A0, Bp0[2], Bp0[3]);
        mma16(acc[1][1], A1, Bp0[2], Bp0[3]);
        mma16(acc[0][2], A0, Bp1[0], Bp1[1]);
        mma16(acc[1][2], A1, Bp1[0], Bp1[1]);
        mma16(acc[0][3], A0, Bp1[2], Bp1[3]);
        mma16(acc[1][3], A1, Bp1[2], Bp1[3]);
        if (NTQ == 5) {
            mma16(acc[0][4], A0, B4[0], B4[1]);
            mma16(acc[1][4], A1, B4[0], B4[1]);
        }
    }
    // tail k8 (d_chi k-rows 128..135)
    {
        uint32_t TA[4], TB[4], TB4[1];
        ldm4(TA, aAt);
        ldm4(TB, aBt);
        if (NTQ == 5) ldm1(TB4, aBt4);
#pragma unroll
        for (int nt = 0; nt < 4; nt++) {
            mma8(acc[0][nt], TA[0], TA[1], TB[nt]);
            mma8(acc[1][nt], TA[2], TA[3], TB[nt]);
        }
        if (NTQ == 5) {
            mma8(acc[0][4], TA[0], TA[1], TB4[0]);
            mma8(acc[1][4], TA[2], TA[3], TB4[0]);
        }
    }
    // epilogue: a1
    {
        float* ab = a1 + (size_t)m0 * F_;
#pragma unroll
        for (int mt = 0; mt < 2; mt++) {
            int r0 = band * 32 + mt * 16 + g;
            int r1 = r0 + 8;
            bool v0 = (r0 < rv), v1 = (r1 < rv);
#pragma unroll
            for (int nt = 0; nt < 4; nt++) {
                int col = q * 32 + nt * 8 + t4 * 2;
                if (v0) *(float2*)&ab[(size_t)r0 * F_ + col] =
                            make_float2(acc[mt][nt][0], acc[mt][nt][1]);
                if (v1) *(float2*)&ab[(size_t)r1 * F_ + col] =
                            make_float2(acc[mt][nt][2], acc[mt][nt][3]);
            }
        }
    }
    // chi_out from cols 128..131 (only the NTQ==5 quarter)
    if (NTQ == 5) {
#pragma unroll
        for (int mt = 0; mt < 2; mt++) {
            float c0 = acc[mt][4][0], c1 = acc[mt][4][1];
            float c2 = acc[mt][4][2], c3 = acc[mt][4][3];
            float o0 = __shfl_xor_sync(0xFFFFFFFFu, c0, 1);
            float o2 = __shfl_xor_sync(0xFFFFFFFFu, c2, 1);
            int rr0 = band * 32 + mt * 16 + g;
            int rr[2] = {rr0, rr0 + 8};
            if (t4 == 0) {
                float b0r[2] = {c0, c2}, b1r[2] = {c1, c3}, b2r[2] = {o0, o2};
#pragma unroll
                for (int h = 0; h < 2; h++) {
                    if (rr[h] < rv) {
                        const float* cr = &csm[rr[h] * CSTR_W];
                        float4 ca = *(const float4*)&cr[0];
                        float4 cb = *(const float4*)&cr[4];
                        float4 u, w;
                        u.x = b0r[h] * ca.x; u.y = b1r[h] * ca.y;
                        u.z = b1r[h] * ca.z; u.w = b1r[h] * ca.w;
                        w.x = b2r[h] * cb.x; w.y = b2r[h] * cb.y;
                        w.z = b2r[h] * cb.z; w.w = b2r[h] * cb.w;
                        float* op = &chiout[(size_t)(m0 + rr[h]) * 16];
                        *(float4*)&op[0] = u;
                        *(float4*)&op[4] = w;
                    }
                }
            } else if (t4 == 1) {
                float b2r[2] = {c0, c2}, b3r[2] = {c1, c3};
#pragma unroll
                for (int h = 0; h < 2; h++) {
                    if (rr[h] < rv) {
                        const float* cr = &csm[rr[h] * CSTR_W];
                        float4 ca = *(const float4*)&cr[8];
                        float4 cb = *(const float4*)&cr[12];
                        float4 u, w;
                        u.x = b2r[h] * ca.x; u.y = b3r[h] * ca.y;
                        u.z = b3r[h] * ca.z; u.w = b3r[h] * ca.w;
                        w.x = b3r[h] * cb.x; w.y = b3r[h] * cb.y;
                        w.z = b3r[h] * cb.z; w.w = b3r[h] * cb.w;
                        float* op = &chiout[(size_t)(m0 + rr[h]) * 16];
                        *(float4*)&op[8]  = u;
                        *(float4*)&op[12] = w;
                    }
                }
            }
        }
    }
}

__global__ __launch_bounds__(NTHR, 1)
void ib_mma_kernel(const float* __restrict__ x, const float* __restrict__ chi,
                   const float* __restrict__ W, const float* __restrict__ b,
                   float* __restrict__ a1, float* __restrict__ chiout, int n)
{
    extern __shared__ char sm[];
    const uint32_t smb = s2u(sm);
    float* csm  = (float*)(sm + OFF_CHI);
    float* bias = (float*)(sm + OFF_BIAS);

    const int tid  = threadIdx.x;
    const int wid  = tid >> 5;
    const int lane = tid & 31;
    const int g    = lane >> 2;
    const int t4   = lane & 3;
    const int band = wid & 3;          // row band (32 rows)
    const int q    = wid >> 2;         // N quarter
    const int m    = lane >> 3;        // ldmatrix matrix id
    const int rin  = lane & 7;         // ldmatrix row within matrix

    // lane-constant ldmatrix base addresses
    const uint32_t aA0 = smb + OFF_A
        + (uint32_t)(band * 32 + (m & 1) * 8 + rin) * ASTR_B + (uint32_t)(m >> 1) * 16u;
    const uint32_t aA1 = aA0 + 16u * ASTR_B;
    const uint32_t aB0 = smb + OFF_BT
        + (uint32_t)(q * 32 + (m >> 1) * 8 + rin) * BSTR_B + (uint32_t)(m & 1) * 16u;
    const uint32_t aB1 = aB0 + 16u * BSTR_B;
    const uint32_t aB4 = smb + OFF_BT
        + (uint32_t)(q * 32 + 32 + rin) * BSTR_B + (uint32_t)(m & 1) * 16u;
    const uint32_t aAt = smb + OFF_A
        + (uint32_t)(band * 32 + (m >> 1) * 16 + (m & 1) * 8 + rin) * ASTR_B + 256u;
    const uint32_t aBt = smb + OFF_BT
        + (uint32_t)(q * 32 + m * 8 + rin) * BSTR_B + 256u;
    const uint32_t aBt4 = smb + OFF_BT
        + (uint32_t)(q * 32 + 32 + rin) * BSTR_B + 256u;

    const int ntiles = (n + MT_ - 1) / MT_;
    int t = blockIdx.x;

    float4 xr[8];
    float4 cv;

    // prologue LDG of tile0
    {
        int m0 = t * MT_;
        int rv = (n - m0 < MT_) ? (n - m0) : MT_;
#pragma unroll
        for (int j = 0; j < 8; j++) {
            int e = tid + j * NTHR;
            int row = e >> 5, c4 = e & 31;
            xr[j] = make_float4(0.f, 0.f, 0.f, 0.f);
            if (row < rv)
                xr[j] = *(const float4*)(x + (size_t)(m0 + row) * F_ + c4 * 4);
        }
        int rowc = tid >> 2, seg = tid & 3;
        cv = make_float4(0.f, 0.f, 0.f, 0.f);
        if (rowc < rv)
            cv = *(const float4*)(chi + (size_t)(m0 + rowc) * 16 + seg * 4);
    }

    // one-time: W -> Bt (f16 [n][k]), bias
    for (int e = tid; e < 136 * 68; e += NTHR) {
        int col = e / 68, kp = e - col * 68;
        int k0 = 2 * kp, k1 = k0 + 1;
        float w0 = (k0 < NE_ && col < NE_) ? W[k0 * NE_ + col] : 0.f;
        float w1 = (k1 < NE_ && col < NE_) ? W[k1 * NE_ + col] : 0.f;
        *(uint32_t*)(sm + OFF_BT + col * BSTR_B + kp * 4) = packh(w0, w1);
    }
    if (tid < 136) bias[tid] = (tid < NE_) ? b[tid] : 0.f;

    // prologue STS of tile0 (x -> f16 A, chi -> stage, d_chi -> A k128..135)
    {
#pragma unroll
        for (int j = 0; j < 8; j++) {
            int e = tid + j * NTHR;
            int row = e >> 5, c4 = e & 31;
            uint32_t h0 = packh(xr[j].x, xr[j].y);
            uint32_t h1 = packh(xr[j].z, xr[j].w);
            *(uint2*)(sm + OFF_A + row * ASTR_B + c4 * 8) = make_uint2(h0, h1);
        }
        int rowc = tid >> 2, seg = tid & 3;
        *(float4*)&csm[rowc * CSTR_W + seg * 4] = cv;
        float xx = cv.x * cv.x, yy = cv.y * cv.y, zz = cv.z * cv.z, ww = cv.w * cv.w;
        float av, bv;
        if (seg == 0)      { av = xx;                bv = yy + zz + ww; }
        else if (seg == 1) { av = xx + yy + zz + ww; bv = 0.f; }
        else if (seg == 2) { av = xx;                bv = yy + zz + ww; }
        else               { av = 0.f;               bv = xx + yy + zz + ww; }
        float a1v = __shfl_xor_sync(0xFFFFFFFFu, av, 1);
        float a2v = __shfl_xor_sync(0xFFFFFFFFu, av, 2);
        float b2v = __shfl_xor_sync(0xFFFFFFFFu, bv, 2);
        float b3v = __shfl_xor_sync(0xFFFFFFFFu, bv, 3);
        if (seg == 0) {
            uint32_t h0 = packh(av, bv);
            uint32_t h1 = packh(a1v + a2v, b2v + b3v);
            *(uint4*)(sm + OFF_A + rowc * ASTR_B + 256) = make_uint4(h0, h1, 0u, 0u);
        }
    }
    __syncthreads();

    // persistent tile loop
    for (; t < ntiles; t += gridDim.x) {
        const int m0 = t * MT_;
        const int rv = (n - m0 < MT_) ? (n - m0) : MT_;
        const int tn = t + gridDim.x;
        const bool more = (tn < ntiles);

        if (more) {
            int m0n = tn * MT_;
            int rvn = (n - m0n < MT_) ? (n - m0n) : MT_;
#pragma unroll
            for (int j = 0; j < 8; j++) {
                int e = tid + j * NTHR;
                int row = e >> 5, c4 = e & 31;
                xr[j] = make_float4(0.f, 0.f, 0.f, 0.f);
                if (row < rvn)
                    xr[j] = *(const float4*)(x + (size_t)(m0n + row) * F_ + c4 * 4);
            }
            int rowc = tid >> 2, seg = tid & 3;
            cv = make_float4(0.f, 0.f, 0.f, 0.f);
            if (rowc < rvn)
                cv = *(const float4*)(chi + (size_t)(m0n + rowc) * 16 + seg * 4);
        }

        if (q == 3)
            compute_tile<5>(aA0, aA1, aB0, aB1, aB4, aAt, aBt, aBt4,
                            bias, csm, a1, chiout, m0, rv, band, q, g, t4);
        else
            compute_tile<4>(aA0, aA1, aB0, aB1, aB4, aAt, aBt, aBt4,
                            bias, csm, a1, chiout, m0, rv, band, q, g, t4);

        __syncthreads();

        if (more) {
#pragma unroll
            for (int j = 0; j < 8; j++) {
                int e = tid + j * NTHR;
                int row = e >> 5, c4 = e & 31;
                uint32_t h0 = packh(xr[j].x, xr[j].y);
                uint32_t h1 = packh(xr[j].z, xr[j].w);
                *(uint2*)(sm + OFF_A + row * ASTR_B + c4 * 8) = make_uint2(h0, h1);
            }
            int rowc = tid >> 2, seg = tid & 3;
            *(float4*)&csm[rowc * CSTR_W + seg * 4] = cv;
            float xx = cv.x * cv.x, yy = cv.y * cv.y, zz = cv.z * cv.z, ww = cv.w * cv.w;
            float av, bv;
            if (seg == 0)      { av = xx;                bv = yy + zz + ww; }
            else if (seg == 1) { av = xx + yy + zz + ww; bv = 0.f; }
            else if (seg == 2) { av = xx;                bv = yy + zz + ww; }
            else               { av = 0.f;               bv = xx + yy + zz + ww; }
            float a1v = __shfl_xor_sync(0xFFFFFFFFu, av, 1);
            float a2v = __shfl_xor_sync(0xFFFFFFFFu, av, 2);
            float b2v = __shfl_xor_sync(0xFFFFFFFFu, bv, 2);
            float b3v = __shfl_xor_sync(0xFFFFFFFFu, bv, 3);
            if (seg == 0) {
                uint32_t h0 = packh(av, bv);
                uint32_t h1 = packh(a1v + a2v, b2v + b3v);
                *(uint4*)(sm + OFF_A + rowc * ASTR_B + 256) = make_uint4(h0, h1, 0u, 0u);
            }
            __syncthreads();
        }
    }
}

extern "C" void kernel_launch(void* const* d_in, const int* in_sizes, int n_in,
                              void* d_out, int out_size) {
    const float* x   = (const float*)d_in[0];
    const float* chi = (const float*)d_in[1];
    // d_in[2] = point_mask (all ones; unused by the math)
    const float* W   = (const float*)d_in[3];
    const float* b   = (const float*)d_in[4];

    const int n = in_sizes[0] / F_;
    float* out    = (float*)d_out;
    float* a1     = out;
    float* chiout = out + (size_t)n * F_;

    cudaFuncSetAttribute(ib_mma_kernel,
                         cudaFuncAttributeMaxDynamicSharedMemorySize, SMEM_REQ);
    int ntiles = (n + MT_ - 1) / MT_;
    int grid = ntiles < 152 ? ntiles : 152;
    ib_mma_kernel<<<grid, NTHR, SMEM_REQ>>>(x, chi, W, b, a1, chiout, n);
}